// round 10
// baseline (speedup 1.0000x reference)
#include <cuda_runtime.h>

#define BB 2
#define NN 2048
#define DIN 1024
#define DOUT 1024
#define HH 16
#define HD 64

// Scratch (static device allocations — allowed)
__device__ float g_q[BB*HH*NN*HD];
__device__ float g_k[BB*HH*NN*HD];
__device__ float g_v[BB*HH*NN*HD];
__device__ float g_ctx[BB*NN*DOUT];

__device__ __forceinline__ unsigned f2tf32(float f) {
    unsigned r;
    asm("cvt.rna.tf32.f32 %0, %1;" : "=r"(r) : "f"(f));
    return r;
}

__device__ __forceinline__ void mma_tf32(float c[4],
    unsigned a0, unsigned a1, unsigned a2, unsigned a3,
    unsigned b0, unsigned b1)
{
    asm volatile(
        "mma.sync.aligned.m16n8k8.row.col.f32.tf32.tf32.f32 "
        "{%0,%1,%2,%3}, {%4,%5,%6,%7}, {%8,%9}, {%0,%1,%2,%3};"
        : "+f"(c[0]), "+f"(c[1]), "+f"(c[2]), "+f"(c[3])
        : "r"(a0), "r"(a1), "r"(a2), "r"(a3), "r"(b0), "r"(b1));
}

// ---------------------------------------------------------------------------
// Fused QKV GEMM, tf32 MMA. SMEM holds PRE-CONVERTED tf32 (as unsigned):
// conversion happens once per tile load, inner loop is pure LDS + HMMA.
// ---------------------------------------------------------------------------
__global__ __launch_bounds__(256) void qkv_gemm_tc(
    const float* __restrict__ x,
    const float* __restrict__ Wq,
    const float* __restrict__ Wk,
    const float* __restrict__ Wv)
{
    const float* W = (blockIdx.z == 0) ? Wq : (blockIdx.z == 1 ? Wk : Wv);
    float* out = (blockIdx.z == 0) ? g_q : (blockIdx.z == 1 ? g_k : g_v);

    __shared__ unsigned As[128][36];
    __shared__ unsigned Bs[32][136];

    const int tid  = threadIdx.x;
    const int warp = tid >> 5;
    const int lane = tid & 31;
    const int g    = lane >> 2;
    const int tg   = lane & 3;
    const int wm   = (warp >> 2) * 64;
    const int wn   = (warp & 3) * 32;
    const int bm   = blockIdx.y * 128;
    const int bn   = blockIdx.x * 128;

    float c[16][4];
    #pragma unroll
    for (int t = 0; t < 16; t++)
        #pragma unroll
        for (int i = 0; i < 4; i++) c[t][i] = 0.f;

    for (int k0 = 0; k0 < DIN; k0 += 32) {
        #pragma unroll
        for (int s = 0; s < 4; s++) {
            int slot = tid + s * 256;
            int r  = slot >> 3;
            int c4 = (slot & 7) << 2;
            float4 v = *(const float4*)&x[(size_t)(bm + r) * DIN + k0 + c4];
            uint4 u = { f2tf32(v.x), f2tf32(v.y), f2tf32(v.z), f2tf32(v.w) };
            *(uint4*)&As[r][c4] = u;
        }
        #pragma unroll
        for (int s = 0; s < 4; s++) {
            int slot = tid + s * 256;
            int r  = slot >> 5;
            int c4 = (slot & 31) << 2;
            float4 v = *(const float4*)&W[(size_t)(k0 + r) * DOUT + bn + c4];
            uint4 u = { f2tf32(v.x), f2tf32(v.y), f2tf32(v.z), f2tf32(v.w) };
            *(uint4*)&Bs[r][c4] = u;
        }
        __syncthreads();

        #pragma unroll
        for (int kk = 0; kk < 32; kk += 8) {
            unsigned a[4][4], b[4][2];
            #pragma unroll
            for (int mt = 0; mt < 4; mt++) {
                int row = wm + mt * 16 + g;
                a[mt][0] = As[row    ][kk + tg    ];
                a[mt][1] = As[row + 8][kk + tg    ];
                a[mt][2] = As[row    ][kk + tg + 4];
                a[mt][3] = As[row + 8][kk + tg + 4];
            }
            #pragma unroll
            for (int nt = 0; nt < 4; nt++) {
                int col = wn + nt * 8 + g;
                b[nt][0] = Bs[kk + tg    ][col];
                b[nt][1] = Bs[kk + tg + 4][col];
            }
            #pragma unroll
            for (int mt = 0; mt < 4; mt++)
                #pragma unroll
                for (int nt = 0; nt < 4; nt++)
                    mma_tf32(c[mt * 4 + nt],
                             a[mt][0], a[mt][1], a[mt][2], a[mt][3],
                             b[nt][0], b[nt][1]);
        }
        __syncthreads();
    }

    #pragma unroll
    for (int mt = 0; mt < 4; mt++) {
        #pragma unroll
        for (int nt = 0; nt < 4; nt++) {
            int col = bn + wn + nt * 8 + tg * 2;
            int h_ = col >> 6;
            int d_ = col & 63;
            #pragma unroll
            for (int half = 0; half < 2; half++) {
                int row = bm + wm + mt * 16 + g + half * 8;
                int b_ = row >> 11;
                int n_ = row & 2047;
                float* p = &out[(((size_t)(b_ * HH + h_) * NN) + n_) * HD + d_];
                p[0] = c[mt * 4 + nt][half * 2 + 0];
                p[1] = c[mt * 4 + nt][half * 2 + 1];
            }
        }
    }
}

// ---------------------------------------------------------------------------
// Output GEMM, tf32 MMA, A (ctx) hi/lo split done ONCE at SMEM store time.
// ---------------------------------------------------------------------------
__global__ __launch_bounds__(256) void out_gemm_tc(
    const float* __restrict__ Wo,
    const float* __restrict__ bo,
    float* __restrict__ out)
{
    __shared__ unsigned Ahi[128][36];
    __shared__ unsigned Alo[128][36];
    __shared__ unsigned Bs[32][136];

    const int tid  = threadIdx.x;
    const int warp = tid >> 5;
    const int lane = tid & 31;
    const int g    = lane >> 2;
    const int tg   = lane & 3;
    const int wm   = (warp >> 2) * 64;
    const int wn   = (warp & 3) * 32;
    const int bm   = blockIdx.y * 128;
    const int bn   = blockIdx.x * 128;

    float c[16][4];
    #pragma unroll
    for (int t = 0; t < 16; t++)
        #pragma unroll
        for (int i = 0; i < 4; i++) c[t][i] = 0.f;

    for (int k0 = 0; k0 < DOUT; k0 += 32) {
        #pragma unroll
        for (int s = 0; s < 4; s++) {
            int slot = tid + s * 256;
            int r  = slot >> 3;
            int c4 = (slot & 7) << 2;
            float4 v = *(const float4*)&g_ctx[(size_t)(bm + r) * DOUT + k0 + c4];
            uint4 hi = { f2tf32(v.x), f2tf32(v.y), f2tf32(v.z), f2tf32(v.w) };
            uint4 lo = { f2tf32(v.x - __uint_as_float(hi.x)),
                         f2tf32(v.y - __uint_as_float(hi.y)),
                         f2tf32(v.z - __uint_as_float(hi.z)),
                         f2tf32(v.w - __uint_as_float(hi.w)) };
            *(uint4*)&Ahi[r][c4] = hi;
            *(uint4*)&Alo[r][c4] = lo;
        }
        #pragma unroll
        for (int s = 0; s < 4; s++) {
            int slot = tid + s * 256;
            int r  = slot >> 5;
            int c4 = (slot & 31) << 2;
            float4 v = *(const float4*)&Wo[(size_t)(k0 + r) * DOUT + bn + c4];
            uint4 u = { f2tf32(v.x), f2tf32(v.y), f2tf32(v.z), f2tf32(v.w) };
            *(uint4*)&Bs[r][c4] = u;
        }
        __syncthreads();

        #pragma unroll
        for (int kk = 0; kk < 32; kk += 8) {
            unsigned ahi[4][4], alo[4][4], b[4][2];
            #pragma unroll
            for (int mt = 0; mt < 4; mt++) {
                int row = wm + mt * 16 + g;
                ahi[mt][0] = Ahi[row    ][kk + tg    ];
                ahi[mt][1] = Ahi[row + 8][kk + tg    ];
                ahi[mt][2] = Ahi[row    ][kk + tg + 4];
                ahi[mt][3] = Ahi[row + 8][kk + tg + 4];
                alo[mt][0] = Alo[row    ][kk + tg    ];
                alo[mt][1] = Alo[row + 8][kk + tg    ];
                alo[mt][2] = Alo[row    ][kk + tg + 4];
                alo[mt][3] = Alo[row + 8][kk + tg + 4];
            }
            #pragma unroll
            for (int nt = 0; nt < 4; nt++) {
                int col = wn + nt * 8 + g;
                b[nt][0] = Bs[kk + tg    ][col];
                b[nt][1] = Bs[kk + tg + 4][col];
            }
            #pragma unroll
            for (int mt = 0; mt < 4; mt++)
                #pragma unroll
                for (int nt = 0; nt < 4; nt++) {
                    mma_tf32(c[mt * 4 + nt],
                             ahi[mt][0], ahi[mt][1], ahi[mt][2], ahi[mt][3],
                             b[nt][0], b[nt][1]);
                    mma_tf32(c[mt * 4 + nt],
                             alo[mt][0], alo[mt][1], alo[mt][2], alo[mt][3],
                             b[nt][0], b[nt][1]);
                }
        }
        __syncthreads();
    }

    #pragma unroll
    for (int mt = 0; mt < 4; mt++) {
        #pragma unroll
        for (int nt = 0; nt < 4; nt++) {
            int col = bn + wn + nt * 8 + tg * 2;
            float b0 = bo[col], b1 = bo[col + 1];
            #pragma unroll
            for (int half = 0; half < 2; half++) {
                int row = bm + wm + mt * 16 + g + half * 8;
                float* p = &out[(size_t)row * DOUT + col];
                p[0] = c[mt * 4 + nt][half * 2 + 0] + b0;
                p[1] = c[mt * 4 + nt][half * 2 + 1] + b1;
            }
        }
    }
}

// ---------------------------------------------------------------------------
// Tensor-core flash attention. SMEM holds pre-converted tf32:
// Qhi/Qlo computed ONCE per block (was: re-split every K-tile), K/V converted
// at tile load, P stored pre-rounded (lsum sums exactly what PV consumes).
// NOTE: the Ks fragment read MUST stay transposed (Ks[col*68 + kk+tg]) —
// for S = Q K^T the MMA reduction dim is d, keys are the n dim.
// ---------------------------------------------------------------------------
#define QHI_OFF 0
#define QLO_OFF (128*68)
#define KS_OFF  (QLO_OFF + 128*68)
#define VS_OFF  (KS_OFF + 64*68)
#define PS_OFF  (VS_OFF + 64*68)
#define RS_OFF  (PS_OFF + 128*68)
#define LS_OFF  (RS_OFF + 2048)
#define ATTN_SMEM_FLOATS (LS_OFF + 128)
#define ATTN_SMEM_BYTES (ATTN_SMEM_FLOATS * 4)

__global__ __launch_bounds__(256) void attn_tc(
    const float* __restrict__ wp,
    const float* __restrict__ vp)
{
    extern __shared__ float sm[];
    unsigned* Qhi = (unsigned*)sm + QHI_OFF;
    unsigned* Qlo = (unsigned*)sm + QLO_OFF;
    unsigned* Ks  = (unsigned*)sm + KS_OFF;
    unsigned* Vs  = (unsigned*)sm + VS_OFF;
    unsigned* Ps  = (unsigned*)sm + PS_OFF;
    float* Rs = sm + RS_OFF;
    float* Ls = sm + LS_OFF;

    const int qb  = blockIdx.x;
    const int h   = blockIdx.y;
    const int b   = blockIdx.z;
    const int tid = threadIdx.x;
    const int warp = tid >> 5;
    const int lane = tid & 31;
    const int g  = lane >> 2;
    const int tg = lane & 3;
    const int wm = (warp >> 1) * 32;
    const int wn = (warp & 1) * 32;

    const size_t head_off = (size_t)(b * HH + h) * NN * HD;
    const float* qbase = g_q + head_off;
    const float* kbase = g_k + head_off;
    const float* vbase = g_v + head_off;

    const float wh = wp[h];
    const float vh = vp[h];
    const float c1 = 1.f + __expf(vh);

    for (int i = tid; i < NN; i += 256)
        Rs[i] = c1 / (1.f + __expf(vh - wh * (float)i)) * 0.125f;
    if (tid < 128) Ls[tid] = 0.f;

    // Load Q tile, split hi/lo ONCE
    #pragma unroll
    for (int s = 0; s < 8; s++) {
        int slot = tid + s * 256;
        int r  = slot >> 4;
        int c4 = (slot & 15) << 2;
        float4 v = *(const float4*)&qbase[(size_t)(qb * 128 + r) * HD + c4];
        uint4 hi = { f2tf32(v.x), f2tf32(v.y), f2tf32(v.z), f2tf32(v.w) };
        uint4 lo = { f2tf32(v.x - __uint_as_float(hi.x)),
                     f2tf32(v.y - __uint_as_float(hi.y)),
                     f2tf32(v.z - __uint_as_float(hi.z)),
                     f2tf32(v.w - __uint_as_float(hi.w)) };
        *(uint4*)&Qhi[r * 68 + c4] = hi;
        *(uint4*)&Qlo[r * 68 + c4] = lo;
    }
    __syncthreads();

    float co[2][4][4];
    #pragma unroll
    for (int mt = 0; mt < 2; mt++)
        #pragma unroll
        for (int nt = 0; nt < 4; nt++)
            #pragma unroll
            for (int i = 0; i < 4; i++) co[mt][nt][i] = 0.f;

    const int ktmax = (qb + 1) * 2;
    for (int kt = 0; kt < ktmax; kt++) {
        const int k0 = kt * 64;

        #pragma unroll
        for (int s = 0; s < 4; s++) {
            int slot = tid + s * 256;
            int r  = slot >> 4;
            int c4 = (slot & 15) << 2;
            float4 kv = *(const float4*)&kbase[(size_t)(k0 + r) * HD + c4];
            float4 vv = *(const float4*)&vbase[(size_t)(k0 + r) * HD + c4];
            uint4 ku = { f2tf32(kv.x), f2tf32(kv.y), f2tf32(kv.z), f2tf32(kv.w) };
            uint4 vu = { f2tf32(vv.x), f2tf32(vv.y), f2tf32(vv.z), f2tf32(vv.w) };
            *(uint4*)&Ks[r * 68 + c4] = ku;
            *(uint4*)&Vs[r * 68 + c4] = vu;
        }
        __syncthreads();

        float cs[2][4][4];
        #pragma unroll
        for (int mt = 0; mt < 2; mt++)
            #pragma unroll
            for (int nt = 0; nt < 4; nt++)
                #pragma unroll
                for (int i = 0; i < 4; i++) cs[mt][nt][i] = 0.f;

        #pragma unroll
        for (int kk = 0; kk < 64; kk += 8) {
            unsigned ahi[2][4], alo[2][4], bb[4][2];
            #pragma unroll
            for (int mt = 0; mt < 2; mt++) {
                int row = wm + mt * 16 + g;
                ahi[mt][0] = Qhi[row * 68 + kk + tg];
                ahi[mt][1] = Qhi[(row + 8) * 68 + kk + tg];
                ahi[mt][2] = Qhi[row * 68 + kk + tg + 4];
                ahi[mt][3] = Qhi[(row + 8) * 68 + kk + tg + 4];
                alo[mt][0] = Qlo[row * 68 + kk + tg];
                alo[mt][1] = Qlo[(row + 8) * 68 + kk + tg];
                alo[mt][2] = Qlo[row * 68 + kk + tg + 4];
                alo[mt][3] = Qlo[(row + 8) * 68 + kk + tg + 4];
            }
            #pragma unroll
            for (int nt = 0; nt < 4; nt++) {
                int col = wn + nt * 8 + g;   // key index within tile
                bb[nt][0] = Ks[col * 68 + kk + tg    ];
                bb[nt][1] = Ks[col * 68 + kk + tg + 4];
            }
            #pragma unroll
            for (int mt = 0; mt < 2; mt++)
                #pragma unroll
                for (int nt = 0; nt < 4; nt++) {
                    mma_tf32(cs[mt][nt],
                             ahi[mt][0], ahi[mt][1], ahi[mt][2], ahi[mt][3],
                             bb[nt][0], bb[nt][1]);
                    mma_tf32(cs[mt][nt],
                             alo[mt][0], alo[mt][1], alo[mt][2], alo[mt][3],
                             bb[nt][0], bb[nt][1]);
                }
        }

        float rp[2][2] = {{0.f, 0.f}, {0.f, 0.f}};
        #pragma unroll
        for (int mt = 0; mt < 2; mt++) {
            #pragma unroll
            for (int nt = 0; nt < 4; nt++) {
                #pragma unroll
                for (int i = 0; i < 4; i++) {
                    int half = i >> 1;
                    int row_l = wm + mt * 16 + g + half * 8;
                    int col = wn + nt * 8 + tg * 2 + (i & 1);
                    int R = (qb * 128 + row_l) - (k0 + col);
                    float s = fmaxf(cs[mt][nt][i], 0.f);
                    float p = (R >= 0) ? __expf(s * Rs[R]) : 0.f;
                    unsigned pt = f2tf32(p);
                    Ps[row_l * 68 + col] = pt;
                    rp[mt][half] += __uint_as_float(pt);
                }
            }
        }
        #pragma unroll
        for (int mt = 0; mt < 2; mt++)
            #pragma unroll
            for (int half = 0; half < 2; half++) {
                float v = rp[mt][half];
                v += __shfl_xor_sync(0xffffffff, v, 1);
                v += __shfl_xor_sync(0xffffffff, v, 2);
                if (tg == 0)
                    atomicAdd(&Ls[wm + mt * 16 + g + half * 8], v);
            }
        __syncthreads();

        #pragma unroll
        for (int kk = 0; kk < 64; kk += 8) {
            unsigned pa[2][4], bb[4][2];
            #pragma unroll
            for (int mt = 0; mt < 2; mt++) {
                int row = wm + mt * 16 + g;
                pa[mt][0] = Ps[row * 68 + kk + tg];
                pa[mt][1] = Ps[(row + 8) * 68 + kk + tg];
                pa[mt][2] = Ps[row * 68 + kk + tg + 4];
                pa[mt][3] = Ps[(row + 8) * 68 + kk + tg + 4];
            }
            #pragma unroll
            for (int nt = 0; nt < 4; nt++) {
                int col = wn + nt * 8 + g;   // d index
                bb[nt][0] = Vs[(kk + tg) * 68 + col];
                bb[nt][1] = Vs[(kk + tg + 4) * 68 + col];
            }
            #pragma unroll
            for (int mt = 0; mt < 2; mt++)
                #pragma unroll
                for (int nt = 0; nt < 4; nt++)
                    mma_tf32(co[mt][nt],
                             pa[mt][0], pa[mt][1], pa[mt][2], pa[mt][3],
                             bb[nt][0], bb[nt][1]);
        }
        __syncthreads();
    }

    #pragma unroll
    for (int mt = 0; mt < 2; mt++) {
        #pragma unroll
        for (int half = 0; half < 2; half++) {
            int row_l = wm + mt * 16 + g + half * 8;
            float inv = 1.f / Ls[row_l];
            int n_ = qb * 128 + row_l;
            float* op = g_ctx + ((size_t)(b * NN + n_) * DOUT) + h * HD;
            #pragma unroll
            for (int nt = 0; nt < 4; nt++) {
                int col = wn + nt * 8 + tg * 2;
                op[col]     = co[mt][nt][half * 2 + 0] * inv;
                op[col + 1] = co[mt][nt][half * 2 + 1] * inv;
            }
        }
    }
}

// ---------------------------------------------------------------------------
extern "C" void kernel_launch(void* const* d_in, const int* in_sizes, int n_in,
                              void* d_out, int out_size)
{
    const float* x  = (const float*)d_in[0];
    const float* Wq = (const float*)d_in[1];
    const float* Wk = (const float*)d_in[2];
    const float* Wv = (const float*)d_in[3];
    const float* Wo = (const float*)d_in[4];
    const float* bo = (const float*)d_in[5];
    const float* w  = (const float*)d_in[6];
    const float* v  = (const float*)d_in[7];
    float* out = (float*)d_out;

    cudaFuncSetAttribute(attn_tc,
        cudaFuncAttributeMaxDynamicSharedMemorySize, ATTN_SMEM_BYTES);

    dim3 g1(DOUT / 128, (BB * NN) / 128, 3);
    qkv_gemm_tc<<<g1, 256>>>(x, Wq, Wk, Wv);

    dim3 g2(NN / 128, HH, BB);
    attn_tc<<<g2, 256, ATTN_SMEM_BYTES>>>(w, v);

    dim3 g3(DOUT / 128, (BB * NN) / 128, 1);
    out_gemm_tc<<<g3, 256>>>(Wo, bo, out);
}

// round 11
// speedup vs baseline: 1.1044x; 1.1044x over previous
#include <cuda_runtime.h>

#define BB 2
#define NN 2048
#define DIN 1024
#define DOUT 1024
#define HH 16
#define HD 64

// Scratch (static device allocations — allowed)
__device__ float g_q[BB*HH*NN*HD];
__device__ float g_k[BB*HH*NN*HD];
__device__ float g_v[BB*HH*NN*HD];
__device__ float g_ctx[BB*NN*DOUT];

__device__ __forceinline__ unsigned f2tf32(float f) {
    unsigned r;
    asm("cvt.rna.tf32.f32 %0, %1;" : "=r"(r) : "f"(f));
    return r;
}

__device__ __forceinline__ void mma_tf32(float c[4],
    unsigned a0, unsigned a1, unsigned a2, unsigned a3,
    unsigned b0, unsigned b1)
{
    asm volatile(
        "mma.sync.aligned.m16n8k8.row.col.f32.tf32.tf32.f32 "
        "{%0,%1,%2,%3}, {%4,%5,%6,%7}, {%8,%9}, {%0,%1,%2,%3};"
        : "+f"(c[0]), "+f"(c[1]), "+f"(c[2]), "+f"(c[3])
        : "r"(a0), "r"(a1), "r"(a2), "r"(a3), "r"(b0), "r"(b1));
}

// ---------------------------------------------------------------------------
// Fused QKV GEMM, tf32 MMA, SMEM pre-converted to tf32 (R9 version, measured
// faster: 213us). 36KB SMEM keeps 2+ blocks/SM.
// ---------------------------------------------------------------------------
__global__ __launch_bounds__(256) void qkv_gemm_tc(
    const float* __restrict__ x,
    const float* __restrict__ Wq,
    const float* __restrict__ Wk,
    const float* __restrict__ Wv)
{
    const float* W = (blockIdx.z == 0) ? Wq : (blockIdx.z == 1 ? Wk : Wv);
    float* out = (blockIdx.z == 0) ? g_q : (blockIdx.z == 1 ? g_k : g_v);

    __shared__ unsigned As[128][36];
    __shared__ unsigned Bs[32][136];

    const int tid  = threadIdx.x;
    const int warp = tid >> 5;
    const int lane = tid & 31;
    const int g    = lane >> 2;
    const int tg   = lane & 3;
    const int wm   = (warp >> 2) * 64;
    const int wn   = (warp & 3) * 32;
    const int bm   = blockIdx.y * 128;
    const int bn   = blockIdx.x * 128;

    float c[16][4];
    #pragma unroll
    for (int t = 0; t < 16; t++)
        #pragma unroll
        for (int i = 0; i < 4; i++) c[t][i] = 0.f;

    for (int k0 = 0; k0 < DIN; k0 += 32) {
        #pragma unroll
        for (int s = 0; s < 4; s++) {
            int slot = tid + s * 256;
            int r  = slot >> 3;
            int c4 = (slot & 7) << 2;
            float4 v = *(const float4*)&x[(size_t)(bm + r) * DIN + k0 + c4];
            uint4 u = { f2tf32(v.x), f2tf32(v.y), f2tf32(v.z), f2tf32(v.w) };
            *(uint4*)&As[r][c4] = u;
        }
        #pragma unroll
        for (int s = 0; s < 4; s++) {
            int slot = tid + s * 256;
            int r  = slot >> 5;
            int c4 = (slot & 31) << 2;
            float4 v = *(const float4*)&W[(size_t)(k0 + r) * DOUT + bn + c4];
            uint4 u = { f2tf32(v.x), f2tf32(v.y), f2tf32(v.z), f2tf32(v.w) };
            *(uint4*)&Bs[r][c4] = u;
        }
        __syncthreads();

        #pragma unroll
        for (int kk = 0; kk < 32; kk += 8) {
            unsigned a[4][4], b[4][2];
            #pragma unroll
            for (int mt = 0; mt < 4; mt++) {
                int row = wm + mt * 16 + g;
                a[mt][0] = As[row    ][kk + tg    ];
                a[mt][1] = As[row + 8][kk + tg    ];
                a[mt][2] = As[row    ][kk + tg + 4];
                a[mt][3] = As[row + 8][kk + tg + 4];
            }
            #pragma unroll
            for (int nt = 0; nt < 4; nt++) {
                int col = wn + nt * 8 + g;
                b[nt][0] = Bs[kk + tg    ][col];
                b[nt][1] = Bs[kk + tg + 4][col];
            }
            #pragma unroll
            for (int mt = 0; mt < 4; mt++)
                #pragma unroll
                for (int nt = 0; nt < 4; nt++)
                    mma_tf32(c[mt * 4 + nt],
                             a[mt][0], a[mt][1], a[mt][2], a[mt][3],
                             b[nt][0], b[nt][1]);
        }
        __syncthreads();
    }

    #pragma unroll
    for (int mt = 0; mt < 4; mt++) {
        #pragma unroll
        for (int nt = 0; nt < 4; nt++) {
            int col = bn + wn + nt * 8 + tg * 2;
            int h_ = col >> 6;
            int d_ = col & 63;
            #pragma unroll
            for (int half = 0; half < 2; half++) {
                int row = bm + wm + mt * 16 + g + half * 8;
                int b_ = row >> 11;
                int n_ = row & 2047;
                float* p = &out[(((size_t)(b_ * HH + h_) * NN) + n_) * HD + d_];
                p[0] = c[mt * 4 + nt][half * 2 + 0];
                p[1] = c[mt * 4 + nt][half * 2 + 1];
            }
        }
    }
}

// ---------------------------------------------------------------------------
// Output GEMM, tf32 MMA (R8 version: per-iter A hi/lo split in registers —
// the SMEM-table variant in R9 regressed). A split, B single-rounded.
// ---------------------------------------------------------------------------
__global__ __launch_bounds__(256) void out_gemm_tc(
    const float* __restrict__ Wo,
    const float* __restrict__ bo,
    float* __restrict__ out)
{
    __shared__ float As[128][36];
    __shared__ float Bs[32][136];

    const int tid  = threadIdx.x;
    const int warp = tid >> 5;
    const int lane = tid & 31;
    const int g    = lane >> 2;
    const int tg   = lane & 3;
    const int wm   = (warp >> 2) * 64;
    const int wn   = (warp & 3) * 32;
    const int bm   = blockIdx.y * 128;
    const int bn   = blockIdx.x * 128;

    float c[16][4];
    #pragma unroll
    for (int t = 0; t < 16; t++)
        #pragma unroll
        for (int i = 0; i < 4; i++) c[t][i] = 0.f;

    for (int k0 = 0; k0 < DOUT; k0 += 32) {
        #pragma unroll
        for (int s = 0; s < 4; s++) {
            int slot = tid + s * 256;
            int r  = slot >> 3;
            int c4 = (slot & 7) << 2;
            *(float4*)&As[r][c4] =
                *(const float4*)&g_ctx[(size_t)(bm + r) * DOUT + k0 + c4];
        }
        #pragma unroll
        for (int s = 0; s < 4; s++) {
            int slot = tid + s * 256;
            int r  = slot >> 5;
            int c4 = (slot & 31) << 2;
            *(float4*)&Bs[r][c4] =
                *(const float4*)&Wo[(size_t)(k0 + r) * DOUT + bn + c4];
        }
        __syncthreads();

        #pragma unroll
        for (int kk = 0; kk < 32; kk += 8) {
            unsigned ahi[4][4], alo[4][4], b[4][2];
            #pragma unroll
            for (int mt = 0; mt < 4; mt++) {
                int row = wm + mt * 16 + g;
                float a0 = As[row    ][kk + tg    ];
                float a1 = As[row + 8][kk + tg    ];
                float a2 = As[row    ][kk + tg + 4];
                float a3 = As[row + 8][kk + tg + 4];
                ahi[mt][0] = f2tf32(a0); ahi[mt][1] = f2tf32(a1);
                ahi[mt][2] = f2tf32(a2); ahi[mt][3] = f2tf32(a3);
                alo[mt][0] = f2tf32(a0 - __uint_as_float(ahi[mt][0]));
                alo[mt][1] = f2tf32(a1 - __uint_as_float(ahi[mt][1]));
                alo[mt][2] = f2tf32(a2 - __uint_as_float(ahi[mt][2]));
                alo[mt][3] = f2tf32(a3 - __uint_as_float(ahi[mt][3]));
            }
            #pragma unroll
            for (int nt = 0; nt < 4; nt++) {
                int col = wn + nt * 8 + g;
                b[nt][0] = f2tf32(Bs[kk + tg    ][col]);
                b[nt][1] = f2tf32(Bs[kk + tg + 4][col]);
            }
            #pragma unroll
            for (int mt = 0; mt < 4; mt++)
                #pragma unroll
                for (int nt = 0; nt < 4; nt++) {
                    mma_tf32(c[mt * 4 + nt],
                             ahi[mt][0], ahi[mt][1], ahi[mt][2], ahi[mt][3],
                             b[nt][0], b[nt][1]);
                    mma_tf32(c[mt * 4 + nt],
                             alo[mt][0], alo[mt][1], alo[mt][2], alo[mt][3],
                             b[nt][0], b[nt][1]);
                }
        }
        __syncthreads();
    }

    #pragma unroll
    for (int mt = 0; mt < 4; mt++) {
        #pragma unroll
        for (int nt = 0; nt < 4; nt++) {
            int col = bn + wn + nt * 8 + tg * 2;
            float b0 = bo[col], b1 = bo[col + 1];
            #pragma unroll
            for (int half = 0; half < 2; half++) {
                int row = bm + wm + mt * 16 + g + half * 8;
                float* p = &out[(size_t)row * DOUT + col];
                p[0] = c[mt * 4 + nt][half * 2 + 0] + b0;
                p[1] = c[mt * 4 + nt][half * 2 + 1] + b1;
            }
        }
    }
}

// ---------------------------------------------------------------------------
// Tensor-core flash attention (R8 version — 113KB SMEM keeps 2 blocks/SM;
// R9's Qlo table pushed it to 1 block/SM and regressed).
// NEW: largest-first block order — qb = 15 - blockIdx.x, so heavy causal
// tiles (more K-tiles) are dispatched first, light ones pack the tail wave.
// NOTE: the Ks fragment read MUST stay transposed (Ks[col*68 + kk+tg]) —
// for S = Q K^T the MMA reduction dim is d, keys are the n dim.
// ---------------------------------------------------------------------------
#define QS_OFF 0
#define KS_OFF (128*68)
#define VS_OFF (KS_OFF + 64*68)
#define PS_OFF (VS_OFF + 64*68)
#define RS_OFF (PS_OFF + 128*68)
#define LS_OFF (RS_OFF + 2048)
#define ATTN_SMEM_FLOATS (LS_OFF + 128)
#define ATTN_SMEM_BYTES (ATTN_SMEM_FLOATS * 4)

__global__ __launch_bounds__(256) void attn_tc(
    const float* __restrict__ wp,
    const float* __restrict__ vp)
{
    extern __shared__ float sm[];
    float* Qs = sm + QS_OFF;
    float* Ks = sm + KS_OFF;
    float* Vs = sm + VS_OFF;
    float* Ps = sm + PS_OFF;
    float* Rs = sm + RS_OFF;
    float* Ls = sm + LS_OFF;

    const int qb  = (NN / 128 - 1) - blockIdx.x;   // largest-first
    const int h   = blockIdx.y;
    const int b   = blockIdx.z;
    const int tid = threadIdx.x;
    const int warp = tid >> 5;
    const int lane = tid & 31;
    const int g  = lane >> 2;
    const int tg = lane & 3;
    const int wm = (warp >> 1) * 32;
    const int wn = (warp & 1) * 32;

    const size_t head_off = (size_t)(b * HH + h) * NN * HD;
    const float* qbase = g_q + head_off;
    const float* kbase = g_k + head_off;
    const float* vbase = g_v + head_off;

    const float wh = wp[h];
    const float vh = vp[h];
    const float c1 = 1.f + __expf(vh);

    for (int i = tid; i < NN; i += 256)
        Rs[i] = c1 / (1.f + __expf(vh - wh * (float)i)) * 0.125f;
    if (tid < 128) Ls[tid] = 0.f;

    #pragma unroll
    for (int s = 0; s < 8; s++) {
        int slot = tid + s * 256;
        int r  = slot >> 4;
        int c4 = (slot & 15) << 2;
        *(float4*)&Qs[r * 68 + c4] =
            *(const float4*)&qbase[(size_t)(qb * 128 + r) * HD + c4];
    }
    __syncthreads();

    float co[2][4][4];
    #pragma unroll
    for (int mt = 0; mt < 2; mt++)
        #pragma unroll
        for (int nt = 0; nt < 4; nt++)
            #pragma unroll
            for (int i = 0; i < 4; i++) co[mt][nt][i] = 0.f;

    const int ktmax = (qb + 1) * 2;
    for (int kt = 0; kt < ktmax; kt++) {
        const int k0 = kt * 64;

        #pragma unroll
        for (int s = 0; s < 4; s++) {
            int slot = tid + s * 256;
            int r  = slot >> 4;
            int c4 = (slot & 15) << 2;
            *(float4*)&Ks[r * 68 + c4] =
                *(const float4*)&kbase[(size_t)(k0 + r) * HD + c4];
            *(float4*)&Vs[r * 68 + c4] =
                *(const float4*)&vbase[(size_t)(k0 + r) * HD + c4];
        }
        __syncthreads();

        float cs[2][4][4];
        #pragma unroll
        for (int mt = 0; mt < 2; mt++)
            #pragma unroll
            for (int nt = 0; nt < 4; nt++)
                #pragma unroll
                for (int i = 0; i < 4; i++) cs[mt][nt][i] = 0.f;

        #pragma unroll
        for (int kk = 0; kk < 64; kk += 8) {
            unsigned ahi[2][4], alo[2][4], bb[4][2];
            #pragma unroll
            for (int mt = 0; mt < 2; mt++) {
                int row = wm + mt * 16 + g;
                float q0 = Qs[row * 68 + kk + tg];
                float q1 = Qs[(row + 8) * 68 + kk + tg];
                float q2 = Qs[row * 68 + kk + tg + 4];
                float q3 = Qs[(row + 8) * 68 + kk + tg + 4];
                ahi[mt][0] = f2tf32(q0); ahi[mt][1] = f2tf32(q1);
                ahi[mt][2] = f2tf32(q2); ahi[mt][3] = f2tf32(q3);
                alo[mt][0] = f2tf32(q0 - __uint_as_float(ahi[mt][0]));
                alo[mt][1] = f2tf32(q1 - __uint_as_float(ahi[mt][1]));
                alo[mt][2] = f2tf32(q2 - __uint_as_float(ahi[mt][2]));
                alo[mt][3] = f2tf32(q3 - __uint_as_float(ahi[mt][3]));
            }
            #pragma unroll
            for (int nt = 0; nt < 4; nt++) {
                int col = wn + nt * 8 + g;   // key index within tile
                bb[nt][0] = f2tf32(Ks[col * 68 + kk + tg    ]);
                bb[nt][1] = f2tf32(Ks[col * 68 + kk + tg + 4]);
            }
            #pragma unroll
            for (int mt = 0; mt < 2; mt++)
                #pragma unroll
                for (int nt = 0; nt < 4; nt++) {
                    mma_tf32(cs[mt][nt],
                             ahi[mt][0], ahi[mt][1], ahi[mt][2], ahi[mt][3],
                             bb[nt][0], bb[nt][1]);
                    mma_tf32(cs[mt][nt],
                             alo[mt][0], alo[mt][1], alo[mt][2], alo[mt][3],
                             bb[nt][0], bb[nt][1]);
                }
        }

        float rp[2][2] = {{0.f, 0.f}, {0.f, 0.f}};
        #pragma unroll
        for (int mt = 0; mt < 2; mt++) {
            #pragma unroll
            for (int nt = 0; nt < 4; nt++) {
                #pragma unroll
                for (int i = 0; i < 4; i++) {
                    int half = i >> 1;
                    int row_l = wm + mt * 16 + g + half * 8;
                    int col = wn + nt * 8 + tg * 2 + (i & 1);
                    int R = (qb * 128 + row_l) - (k0 + col);
                    float s = fmaxf(cs[mt][nt][i], 0.f);
                    float p = (R >= 0) ? __expf(s * Rs[R]) : 0.f;
                    Ps[row_l * 68 + col] = p;
                    rp[mt][half] += p;
                }
            }
        }
        #pragma unroll
        for (int mt = 0; mt < 2; mt++)
            #pragma unroll
            for (int half = 0; half < 2; half++) {
                float v = rp[mt][half];
                v += __shfl_xor_sync(0xffffffff, v, 1);
                v += __shfl_xor_sync(0xffffffff, v, 2);
                if (tg == 0)
                    atomicAdd(&Ls[wm + mt * 16 + g + half * 8], v);
            }
        __syncthreads();

        #pragma unroll
        for (int kk = 0; kk < 64; kk += 8) {
            unsigned pa[2][4], bb[4][2];
            #pragma unroll
            for (int mt = 0; mt < 2; mt++) {
                int row = wm + mt * 16 + g;
                pa[mt][0] = f2tf32(Ps[row * 68 + kk + tg]);
                pa[mt][1] = f2tf32(Ps[(row + 8) * 68 + kk + tg]);
                pa[mt][2] = f2tf32(Ps[row * 68 + kk + tg + 4]);
                pa[mt][3] = f2tf32(Ps[(row + 8) * 68 + kk + tg + 4]);
            }
            #pragma unroll
            for (int nt = 0; nt < 4; nt++) {
                int col = wn + nt * 8 + g;   // d index
                bb[nt][0] = f2tf32(Vs[(kk + tg) * 68 + col]);
                bb[nt][1] = f2tf32(Vs[(kk + tg + 4) * 68 + col]);
            }
            #pragma unroll
            for (int mt = 0; mt < 2; mt++)
                #pragma unroll
                for (int nt = 0; nt < 4; nt++)
                    mma_tf32(co[mt][nt],
                             pa[mt][0], pa[mt][1], pa[mt][2], pa[mt][3],
                             bb[nt][0], bb[nt][1]);
        }
        __syncthreads();
    }

    #pragma unroll
    for (int mt = 0; mt < 2; mt++) {
        #pragma unroll
        for (int half = 0; half < 2; half++) {
            int row_l = wm + mt * 16 + g + half * 8;
            float inv = 1.f / Ls[row_l];
            int n_ = qb * 128 + row_l;
            float* op = g_ctx + ((size_t)(b * NN + n_) * DOUT) + h * HD;
            #pragma unroll
            for (int nt = 0; nt < 4; nt++) {
                int col = wn + nt * 8 + tg * 2;
                op[col]     = co[mt][nt][half * 2 + 0] * inv;
                op[col + 1] = co[mt][nt][half * 2 + 1] * inv;
            }
        }
    }
}

// ---------------------------------------------------------------------------
extern "C" void kernel_launch(void* const* d_in, const int* in_sizes, int n_in,
                              void* d_out, int out_size)
{
    const float* x  = (const float*)d_in[0];
    const float* Wq = (const float*)d_in[1];
    const float* Wk = (const float*)d_in[2];
    const float* Wv = (const float*)d_in[3];
    const float* Wo = (const float*)d_in[4];
    const float* bo = (const float*)d_in[5];
    const float* w  = (const float*)d_in[6];
    const float* v  = (const float*)d_in[7];
    float* out = (float*)d_out;

    cudaFuncSetAttribute(attn_tc,
        cudaFuncAttributeMaxDynamicSharedMemorySize, ATTN_SMEM_BYTES);

    dim3 g1(DOUT / 128, (BB * NN) / 128, 3);
    qkv_gemm_tc<<<g1, 256>>>(x, Wq, Wk, Wv);

    dim3 g2(NN / 128, HH, BB);
    attn_tc<<<g2, 256, ATTN_SMEM_BYTES>>>(w, v);

    dim3 g3(DOUT / 128, (BB * NN) / 128, 1);
    out_gemm_tc<<<g3, 256>>>(Wo, bo, out);
}

// round 12
// speedup vs baseline: 1.2072x; 1.0931x over previous
#include <cuda_runtime.h>

#define BB 2
#define NN 2048
#define DIN 1024
#define DOUT 1024
#define HH 16
#define HD 64

// Scratch (static device allocations — allowed)
__device__ float g_q[BB*HH*NN*HD];
__device__ float g_k[BB*HH*NN*HD];
__device__ float g_v[BB*HH*NN*HD];
__device__ float g_ctx[BB*NN*DOUT];

__device__ __forceinline__ unsigned f2tf32(float f) {
    unsigned r;
    asm("cvt.rna.tf32.f32 %0, %1;" : "=r"(r) : "f"(f));
    return r;
}

__device__ __forceinline__ void mma_tf32(float c[4],
    unsigned a0, unsigned a1, unsigned a2, unsigned a3,
    unsigned b0, unsigned b1)
{
    asm volatile(
        "mma.sync.aligned.m16n8k8.row.col.f32.tf32.tf32.f32 "
        "{%0,%1,%2,%3}, {%4,%5,%6,%7}, {%8,%9}, {%0,%1,%2,%3};"
        : "+f"(c[0]), "+f"(c[1]), "+f"(c[2]), "+f"(c[3])
        : "r"(a0), "r"(a1), "r"(a2), "r"(a3), "r"(b0), "r"(b1));
}

// ---------------------------------------------------------------------------
// Fused QKV GEMM, tf32 MMA, SMEM pre-converted to tf32. Unchanged (measured
// best). 36KB SMEM, 128 regs -> 2 blocks/SM (register-limited).
// ---------------------------------------------------------------------------
__global__ __launch_bounds__(256) void qkv_gemm_tc(
    const float* __restrict__ x,
    const float* __restrict__ Wq,
    const float* __restrict__ Wk,
    const float* __restrict__ Wv)
{
    const float* W = (blockIdx.z == 0) ? Wq : (blockIdx.z == 1 ? Wk : Wv);
    float* out = (blockIdx.z == 0) ? g_q : (blockIdx.z == 1 ? g_k : g_v);

    __shared__ unsigned As[128][36];
    __shared__ unsigned Bs[32][136];

    const int tid  = threadIdx.x;
    const int warp = tid >> 5;
    const int lane = tid & 31;
    const int g    = lane >> 2;
    const int tg   = lane & 3;
    const int wm   = (warp >> 2) * 64;
    const int wn   = (warp & 3) * 32;
    const int bm   = blockIdx.y * 128;
    const int bn   = blockIdx.x * 128;

    float c[16][4];
    #pragma unroll
    for (int t = 0; t < 16; t++)
        #pragma unroll
        for (int i = 0; i < 4; i++) c[t][i] = 0.f;

    for (int k0 = 0; k0 < DIN; k0 += 32) {
        #pragma unroll
        for (int s = 0; s < 4; s++) {
            int slot = tid + s * 256;
            int r  = slot >> 3;
            int c4 = (slot & 7) << 2;
            float4 v = *(const float4*)&x[(size_t)(bm + r) * DIN + k0 + c4];
            uint4 u = { f2tf32(v.x), f2tf32(v.y), f2tf32(v.z), f2tf32(v.w) };
            *(uint4*)&As[r][c4] = u;
        }
        #pragma unroll
        for (int s = 0; s < 4; s++) {
            int slot = tid + s * 256;
            int r  = slot >> 5;
            int c4 = (slot & 31) << 2;
            float4 v = *(const float4*)&W[(size_t)(k0 + r) * DOUT + bn + c4];
            uint4 u = { f2tf32(v.x), f2tf32(v.y), f2tf32(v.z), f2tf32(v.w) };
            *(uint4*)&Bs[r][c4] = u;
        }
        __syncthreads();

        #pragma unroll
        for (int kk = 0; kk < 32; kk += 8) {
            unsigned a[4][4], b[4][2];
            #pragma unroll
            for (int mt = 0; mt < 4; mt++) {
                int row = wm + mt * 16 + g;
                a[mt][0] = As[row    ][kk + tg    ];
                a[mt][1] = As[row + 8][kk + tg    ];
                a[mt][2] = As[row    ][kk + tg + 4];
                a[mt][3] = As[row + 8][kk + tg + 4];
            }
            #pragma unroll
            for (int nt = 0; nt < 4; nt++) {
                int col = wn + nt * 8 + g;
                b[nt][0] = Bs[kk + tg    ][col];
                b[nt][1] = Bs[kk + tg + 4][col];
            }
            #pragma unroll
            for (int mt = 0; mt < 4; mt++)
                #pragma unroll
                for (int nt = 0; nt < 4; nt++)
                    mma_tf32(c[mt * 4 + nt],
                             a[mt][0], a[mt][1], a[mt][2], a[mt][3],
                             b[nt][0], b[nt][1]);
        }
        __syncthreads();
    }

    #pragma unroll
    for (int mt = 0; mt < 4; mt++) {
        #pragma unroll
        for (int nt = 0; nt < 4; nt++) {
            int col = bn + wn + nt * 8 + tg * 2;
            int h_ = col >> 6;
            int d_ = col & 63;
            #pragma unroll
            for (int half = 0; half < 2; half++) {
                int row = bm + wm + mt * 16 + g + half * 8;
                int b_ = row >> 11;
                int n_ = row & 2047;
                float* p = &out[(((size_t)(b_ * HH + h_) * NN) + n_) * HD + d_];
                p[0] = c[mt * 4 + nt][half * 2 + 0];
                p[1] = c[mt * 4 + nt][half * 2 + 1];
            }
        }
    }
}

// ---------------------------------------------------------------------------
// Output GEMM: clone of qkv_gemm_tc (single-rounded tf32 both operands,
// pre-converted SMEM). A-split dropped: adds ~one tf32 rounding of ctx
// (~3e-4 RMS, averaged over K=1024) but halves MMA work (185 -> ~85us).
// ---------------------------------------------------------------------------
__global__ __launch_bounds__(256) void out_gemm_tc(
    const float* __restrict__ Wo,
    const float* __restrict__ bo,
    float* __restrict__ out)
{
    __shared__ unsigned As[128][36];
    __shared__ unsigned Bs[32][136];

    const int tid  = threadIdx.x;
    const int warp = tid >> 5;
    const int lane = tid & 31;
    const int g    = lane >> 2;
    const int tg   = lane & 3;
    const int wm   = (warp >> 2) * 64;
    const int wn   = (warp & 3) * 32;
    const int bm   = blockIdx.y * 128;
    const int bn   = blockIdx.x * 128;

    float c[16][4];
    #pragma unroll
    for (int t = 0; t < 16; t++)
        #pragma unroll
        for (int i = 0; i < 4; i++) c[t][i] = 0.f;

    for (int k0 = 0; k0 < DOUT; k0 += 32) {
        #pragma unroll
        for (int s = 0; s < 4; s++) {
            int slot = tid + s * 256;
            int r  = slot >> 3;
            int c4 = (slot & 7) << 2;
            float4 v = *(const float4*)&g_ctx[(size_t)(bm + r) * DOUT + k0 + c4];
            uint4 u = { f2tf32(v.x), f2tf32(v.y), f2tf32(v.z), f2tf32(v.w) };
            *(uint4*)&As[r][c4] = u;
        }
        #pragma unroll
        for (int s = 0; s < 4; s++) {
            int slot = tid + s * 256;
            int r  = slot >> 5;
            int c4 = (slot & 31) << 2;
            float4 v = *(const float4*)&Wo[(size_t)(k0 + r) * DOUT + bn + c4];
            uint4 u = { f2tf32(v.x), f2tf32(v.y), f2tf32(v.z), f2tf32(v.w) };
            *(uint4*)&Bs[r][c4] = u;
        }
        __syncthreads();

        #pragma unroll
        for (int kk = 0; kk < 32; kk += 8) {
            unsigned a[4][4], b[4][2];
            #pragma unroll
            for (int mt = 0; mt < 4; mt++) {
                int row = wm + mt * 16 + g;
                a[mt][0] = As[row    ][kk + tg    ];
                a[mt][1] = As[row + 8][kk + tg    ];
                a[mt][2] = As[row    ][kk + tg + 4];
                a[mt][3] = As[row + 8][kk + tg + 4];
            }
            #pragma unroll
            for (int nt = 0; nt < 4; nt++) {
                int col = wn + nt * 8 + g;
                b[nt][0] = Bs[kk + tg    ][col];
                b[nt][1] = Bs[kk + tg + 4][col];
            }
            #pragma unroll
            for (int mt = 0; mt < 4; mt++)
                #pragma unroll
                for (int nt = 0; nt < 4; nt++)
                    mma_tf32(c[mt * 4 + nt],
                             a[mt][0], a[mt][1], a[mt][2], a[mt][3],
                             b[nt][0], b[nt][1]);
        }
        __syncthreads();
    }

    #pragma unroll
    for (int mt = 0; mt < 4; mt++) {
        #pragma unroll
        for (int nt = 0; nt < 4; nt++) {
            int col = bn + wn + nt * 8 + tg * 2;
            float b0 = bo[col], b1 = bo[col + 1];
            #pragma unroll
            for (int half = 0; half < 2; half++) {
                int row = bm + wm + mt * 16 + g + half * 8;
                float* p = &out[(size_t)row * DOUT + col];
                p[0] = c[mt * 4 + nt][half * 2 + 0] + b0;
                p[1] = c[mt * 4 + nt][half * 2 + 1] + b1;
            }
        }
    }
}

// ---------------------------------------------------------------------------
// Tensor-core flash attention. Same structure/SMEM SIZE as R10 (113KB,
// 2 blocks/SM) but K/V/P stored PRE-CONVERTED tf32 in place (same word
// count, unsigned) — removes 24 CVTs/kk from the MMA loops. Q hi/lo split
// stays in-loop (register/SMEM-table variants regressed via occupancy).
// Largest-first block order: qb = 15 - blockIdx.x.
// NOTE: the Ks fragment read MUST stay transposed (Ks[col*68 + kk+tg]) —
// for S = Q K^T the MMA reduction dim is d, keys are the n dim.
// ---------------------------------------------------------------------------
#define QS_OFF 0
#define KS_OFF (128*68)
#define VS_OFF (KS_OFF + 64*68)
#define PS_OFF (VS_OFF + 64*68)
#define RS_OFF (PS_OFF + 128*68)
#define LS_OFF (RS_OFF + 2048)
#define ATTN_SMEM_FLOATS (LS_OFF + 128)
#define ATTN_SMEM_BYTES (ATTN_SMEM_FLOATS * 4)

__global__ __launch_bounds__(256) void attn_tc(
    const float* __restrict__ wp,
    const float* __restrict__ vp)
{
    extern __shared__ float sm[];
    float*    Qs = sm + QS_OFF;
    unsigned* Ks = (unsigned*)sm + KS_OFF;
    unsigned* Vs = (unsigned*)sm + VS_OFF;
    unsigned* Ps = (unsigned*)sm + PS_OFF;
    float*    Rs = sm + RS_OFF;
    float*    Ls = sm + LS_OFF;

    const int qb  = (NN / 128 - 1) - blockIdx.x;   // largest-first
    const int h   = blockIdx.y;
    const int b   = blockIdx.z;
    const int tid = threadIdx.x;
    const int warp = tid >> 5;
    const int lane = tid & 31;
    const int g  = lane >> 2;
    const int tg = lane & 3;
    const int wm = (warp >> 1) * 32;
    const int wn = (warp & 1) * 32;

    const size_t head_off = (size_t)(b * HH + h) * NN * HD;
    const float* qbase = g_q + head_off;
    const float* kbase = g_k + head_off;
    const float* vbase = g_v + head_off;

    const float wh = wp[h];
    const float vh = vp[h];
    const float c1 = 1.f + __expf(vh);

    for (int i = tid; i < NN; i += 256)
        Rs[i] = c1 / (1.f + __expf(vh - wh * (float)i)) * 0.125f;
    if (tid < 128) Ls[tid] = 0.f;

    #pragma unroll
    for (int s = 0; s < 8; s++) {
        int slot = tid + s * 256;
        int r  = slot >> 4;
        int c4 = (slot & 15) << 2;
        *(float4*)&Qs[r * 68 + c4] =
            *(const float4*)&qbase[(size_t)(qb * 128 + r) * HD + c4];
    }
    __syncthreads();

    float co[2][4][4];
    #pragma unroll
    for (int mt = 0; mt < 2; mt++)
        #pragma unroll
        for (int nt = 0; nt < 4; nt++)
            #pragma unroll
            for (int i = 0; i < 4; i++) co[mt][nt][i] = 0.f;

    const int ktmax = (qb + 1) * 2;
    for (int kt = 0; kt < ktmax; kt++) {
        const int k0 = kt * 64;

        #pragma unroll
        for (int s = 0; s < 4; s++) {
            int slot = tid + s * 256;
            int r  = slot >> 4;
            int c4 = (slot & 15) << 2;
            float4 kv = *(const float4*)&kbase[(size_t)(k0 + r) * HD + c4];
            float4 vv = *(const float4*)&vbase[(size_t)(k0 + r) * HD + c4];
            uint4 ku = { f2tf32(kv.x), f2tf32(kv.y), f2tf32(kv.z), f2tf32(kv.w) };
            uint4 vu = { f2tf32(vv.x), f2tf32(vv.y), f2tf32(vv.z), f2tf32(vv.w) };
            *(uint4*)&Ks[r * 68 + c4] = ku;
            *(uint4*)&Vs[r * 68 + c4] = vu;
        }
        __syncthreads();

        float cs[2][4][4];
        #pragma unroll
        for (int mt = 0; mt < 2; mt++)
            #pragma unroll
            for (int nt = 0; nt < 4; nt++)
                #pragma unroll
                for (int i = 0; i < 4; i++) cs[mt][nt][i] = 0.f;

        #pragma unroll
        for (int kk = 0; kk < 64; kk += 8) {
            unsigned ahi[2][4], alo[2][4], bb[4][2];
            #pragma unroll
            for (int mt = 0; mt < 2; mt++) {
                int row = wm + mt * 16 + g;
                float q0 = Qs[row * 68 + kk + tg];
                float q1 = Qs[(row + 8) * 68 + kk + tg];
                float q2 = Qs[row * 68 + kk + tg + 4];
                float q3 = Qs[(row + 8) * 68 + kk + tg + 4];
                ahi[mt][0] = f2tf32(q0); ahi[mt][1] = f2tf32(q1);
                ahi[mt][2] = f2tf32(q2); ahi[mt][3] = f2tf32(q3);
                alo[mt][0] = f2tf32(q0 - __uint_as_float(ahi[mt][0]));
                alo[mt][1] = f2tf32(q1 - __uint_as_float(ahi[mt][1]));
                alo[mt][2] = f2tf32(q2 - __uint_as_float(ahi[mt][2]));
                alo[mt][3] = f2tf32(q3 - __uint_as_float(ahi[mt][3]));
            }
            #pragma unroll
            for (int nt = 0; nt < 4; nt++) {
                int col = wn + nt * 8 + g;   // key index within tile
                bb[nt][0] = Ks[col * 68 + kk + tg    ];
                bb[nt][1] = Ks[col * 68 + kk + tg + 4];
            }
            #pragma unroll
            for (int mt = 0; mt < 2; mt++)
                #pragma unroll
                for (int nt = 0; nt < 4; nt++) {
                    mma_tf32(cs[mt][nt],
                             ahi[mt][0], ahi[mt][1], ahi[mt][2], ahi[mt][3],
                             bb[nt][0], bb[nt][1]);
                    mma_tf32(cs[mt][nt],
                             alo[mt][0], alo[mt][1], alo[mt][2], alo[mt][3],
                             bb[nt][0], bb[nt][1]);
                }
        }

        float rp[2][2] = {{0.f, 0.f}, {0.f, 0.f}};
        #pragma unroll
        for (int mt = 0; mt < 2; mt++) {
            #pragma unroll
            for (int nt = 0; nt < 4; nt++) {
                #pragma unroll
                for (int i = 0; i < 4; i++) {
                    int half = i >> 1;
                    int row_l = wm + mt * 16 + g + half * 8;
                    int col = wn + nt * 8 + tg * 2 + (i & 1);
                    int R = (qb * 128 + row_l) - (k0 + col);
                    float s = fmaxf(cs[mt][nt][i], 0.f);
                    float p = (R >= 0) ? __expf(s * Rs[R]) : 0.f;
                    unsigned pt = f2tf32(p);
                    Ps[row_l * 68 + col] = pt;
                    rp[mt][half] += __uint_as_float(pt);
                }
            }
        }
        #pragma unroll
        for (int mt = 0; mt < 2; mt++)
            #pragma unroll
            for (int half = 0; half < 2; half++) {
                float v = rp[mt][half];
                v += __shfl_xor_sync(0xffffffff, v, 1);
                v += __shfl_xor_sync(0xffffffff, v, 2);
                if (tg == 0)
                    atomicAdd(&Ls[wm + mt * 16 + g + half * 8], v);
            }
        __syncthreads();

        #pragma unroll
        for (int kk = 0; kk < 64; kk += 8) {
            unsigned pa[2][4], bb[4][2];
            #pragma unroll
            for (int mt = 0; mt < 2; mt++) {
                int row = wm + mt * 16 + g;
                pa[mt][0] = Ps[row * 68 + kk + tg];
                pa[mt][1] = Ps[(row + 8) * 68 + kk + tg];
                pa[mt][2] = Ps[row * 68 + kk + tg + 4];
                pa[mt][3] = Ps[(row + 8) * 68 + kk + tg + 4];
            }
            #pragma unroll
            for (int nt = 0; nt < 4; nt++) {
                int col = wn + nt * 8 + g;   // d index
                bb[nt][0] = Vs[(kk + tg) * 68 + col];
                bb[nt][1] = Vs[(kk + tg + 4) * 68 + col];
            }
            #pragma unroll
            for (int mt = 0; mt < 2; mt++)
                #pragma unroll
                for (int nt = 0; nt < 4; nt++)
                    mma_tf32(co[mt][nt],
                             pa[mt][0], pa[mt][1], pa[mt][2], pa[mt][3],
                             bb[nt][0], bb[nt][1]);
        }
        __syncthreads();
    }

    #pragma unroll
    for (int mt = 0; mt < 2; mt++) {
        #pragma unroll
        for (int half = 0; half < 2; half++) {
            int row_l = wm + mt * 16 + g + half * 8;
            float inv = 1.f / Ls[row_l];
            int n_ = qb * 128 + row_l;
            float* op = g_ctx + ((size_t)(b * NN + n_) * DOUT) + h * HD;
            #pragma unroll
            for (int nt = 0; nt < 4; nt++) {
                int col = wn + nt * 8 + tg * 2;
                op[col]     = co[mt][nt][half * 2 + 0] * inv;
                op[col + 1] = co[mt][nt][half * 2 + 1] * inv;
            }
        }
    }
}

// ---------------------------------------------------------------------------
extern "C" void kernel_launch(void* const* d_in, const int* in_sizes, int n_in,
                              void* d_out, int out_size)
{
    const float* x  = (const float*)d_in[0];
    const float* Wq = (const float*)d_in[1];
    const float* Wk = (const float*)d_in[2];
    const float* Wv = (const float*)d_in[3];
    const float* Wo = (const float*)d_in[4];
    const float* bo = (const float*)d_in[5];
    const float* w  = (const float*)d_in[6];
    const float* v  = (const float*)d_in[7];
    float* out = (float*)d_out;

    cudaFuncSetAttribute(attn_tc,
        cudaFuncAttributeMaxDynamicSharedMemorySize, ATTN_SMEM_BYTES);

    dim3 g1(DOUT / 128, (BB * NN) / 128, 3);
    qkv_gemm_tc<<<g1, 256>>>(x, Wq, Wk, Wv);

    dim3 g2(NN / 128, HH, BB);
    attn_tc<<<g2, 256, ATTN_SMEM_BYTES>>>(w, v);

    dim3 g3(DOUT / 128, (BB * NN) / 128, 1);
    out_gemm_tc<<<g3, 256>>>(Wo, bo, out);
}

// round 13
// speedup vs baseline: 1.3264x; 1.0988x over previous
#include <cuda_runtime.h>

#define BB 2
#define NN 2048
#define DIN 1024
#define DOUT 1024
#define HH 16
#define HD 64

// Scratch (static device allocations — allowed)
__device__ float g_q[BB*HH*NN*HD];
__device__ float g_k[BB*HH*NN*HD];
__device__ float g_v[BB*HH*NN*HD];
__device__ float g_ctx[BB*NN*DOUT];

__device__ __forceinline__ unsigned f2tf32(float f) {
    unsigned r;
    asm("cvt.rna.tf32.f32 %0, %1;" : "=r"(r) : "f"(f));
    return r;
}

__device__ __forceinline__ void mma_tf32(float c[4],
    unsigned a0, unsigned a1, unsigned a2, unsigned a3,
    unsigned b0, unsigned b1)
{
    asm volatile(
        "mma.sync.aligned.m16n8k8.row.col.f32.tf32.tf32.f32 "
        "{%0,%1,%2,%3}, {%4,%5,%6,%7}, {%8,%9}, {%0,%1,%2,%3};"
        : "+f"(c[0]), "+f"(c[1]), "+f"(c[2]), "+f"(c[3])
        : "r"(a0), "r"(a1), "r"(a2), "r"(a3), "r"(b0), "r"(b1));
}

// ---------------------------------------------------------------------------
// Fused QKV GEMM, tf32 MMA, SMEM pre-converted to tf32. Unchanged (measured
// best: ~214us). 36KB SMEM, 128 regs -> 2 blocks/SM.
// ---------------------------------------------------------------------------
__global__ __launch_bounds__(256) void qkv_gemm_tc(
    const float* __restrict__ x,
    const float* __restrict__ Wq,
    const float* __restrict__ Wk,
    const float* __restrict__ Wv)
{
    const float* W = (blockIdx.z == 0) ? Wq : (blockIdx.z == 1 ? Wk : Wv);
    float* out = (blockIdx.z == 0) ? g_q : (blockIdx.z == 1 ? g_k : g_v);

    __shared__ unsigned As[128][36];
    __shared__ unsigned Bs[32][136];

    const int tid  = threadIdx.x;
    const int warp = tid >> 5;
    const int lane = tid & 31;
    const int g    = lane >> 2;
    const int tg   = lane & 3;
    const int wm   = (warp >> 2) * 64;
    const int wn   = (warp & 3) * 32;
    const int bm   = blockIdx.y * 128;
    const int bn   = blockIdx.x * 128;

    float c[16][4];
    #pragma unroll
    for (int t = 0; t < 16; t++)
        #pragma unroll
        for (int i = 0; i < 4; i++) c[t][i] = 0.f;

    for (int k0 = 0; k0 < DIN; k0 += 32) {
        #pragma unroll
        for (int s = 0; s < 4; s++) {
            int slot = tid + s * 256;
            int r  = slot >> 3;
            int c4 = (slot & 7) << 2;
            float4 v = *(const float4*)&x[(size_t)(bm + r) * DIN + k0 + c4];
            uint4 u = { f2tf32(v.x), f2tf32(v.y), f2tf32(v.z), f2tf32(v.w) };
            *(uint4*)&As[r][c4] = u;
        }
        #pragma unroll
        for (int s = 0; s < 4; s++) {
            int slot = tid + s * 256;
            int r  = slot >> 5;
            int c4 = (slot & 31) << 2;
            float4 v = *(const float4*)&W[(size_t)(k0 + r) * DOUT + bn + c4];
            uint4 u = { f2tf32(v.x), f2tf32(v.y), f2tf32(v.z), f2tf32(v.w) };
            *(uint4*)&Bs[r][c4] = u;
        }
        __syncthreads();

        #pragma unroll
        for (int kk = 0; kk < 32; kk += 8) {
            unsigned a[4][4], b[4][2];
            #pragma unroll
            for (int mt = 0; mt < 4; mt++) {
                int row = wm + mt * 16 + g;
                a[mt][0] = As[row    ][kk + tg    ];
                a[mt][1] = As[row + 8][kk + tg    ];
                a[mt][2] = As[row    ][kk + tg + 4];
                a[mt][3] = As[row + 8][kk + tg + 4];
            }
            #pragma unroll
            for (int nt = 0; nt < 4; nt++) {
                int col = wn + nt * 8 + g;
                b[nt][0] = Bs[kk + tg    ][col];
                b[nt][1] = Bs[kk + tg + 4][col];
            }
            #pragma unroll
            for (int mt = 0; mt < 4; mt++)
                #pragma unroll
                for (int nt = 0; nt < 4; nt++)
                    mma_tf32(c[mt * 4 + nt],
                             a[mt][0], a[mt][1], a[mt][2], a[mt][3],
                             b[nt][0], b[nt][1]);
        }
        __syncthreads();
    }

    #pragma unroll
    for (int mt = 0; mt < 4; mt++) {
        #pragma unroll
        for (int nt = 0; nt < 4; nt++) {
            int col = bn + wn + nt * 8 + tg * 2;
            int h_ = col >> 6;
            int d_ = col & 63;
            #pragma unroll
            for (int half = 0; half < 2; half++) {
                int row = bm + wm + mt * 16 + g + half * 8;
                int b_ = row >> 11;
                int n_ = row & 2047;
                float* p = &out[(((size_t)(b_ * HH + h_) * NN) + n_) * HD + d_];
                p[0] = c[mt * 4 + nt][half * 2 + 0];
                p[1] = c[mt * 4 + nt][half * 2 + 1];
            }
        }
    }
}

// ---------------------------------------------------------------------------
// Output GEMM: clone of qkv_gemm_tc (single-rounded tf32 both operands,
// pre-converted SMEM). Unchanged from R11.
// ---------------------------------------------------------------------------
__global__ __launch_bounds__(256) void out_gemm_tc(
    const float* __restrict__ Wo,
    const float* __restrict__ bo,
    float* __restrict__ out)
{
    __shared__ unsigned As[128][36];
    __shared__ unsigned Bs[32][136];

    const int tid  = threadIdx.x;
    const int warp = tid >> 5;
    const int lane = tid & 31;
    const int g    = lane >> 2;
    const int tg   = lane & 3;
    const int wm   = (warp >> 2) * 64;
    const int wn   = (warp & 3) * 32;
    const int bm   = blockIdx.y * 128;
    const int bn   = blockIdx.x * 128;

    float c[16][4];
    #pragma unroll
    for (int t = 0; t < 16; t++)
        #pragma unroll
        for (int i = 0; i < 4; i++) c[t][i] = 0.f;

    for (int k0 = 0; k0 < DOUT; k0 += 32) {
        #pragma unroll
        for (int s = 0; s < 4; s++) {
            int slot = tid + s * 256;
            int r  = slot >> 3;
            int c4 = (slot & 7) << 2;
            float4 v = *(const float4*)&g_ctx[(size_t)(bm + r) * DOUT + k0 + c4];
            uint4 u = { f2tf32(v.x), f2tf32(v.y), f2tf32(v.z), f2tf32(v.w) };
            *(uint4*)&As[r][c4] = u;
        }
        #pragma unroll
        for (int s = 0; s < 4; s++) {
            int slot = tid + s * 256;
            int r  = slot >> 5;
            int c4 = (slot & 31) << 2;
            float4 v = *(const float4*)&Wo[(size_t)(k0 + r) * DOUT + bn + c4];
            uint4 u = { f2tf32(v.x), f2tf32(v.y), f2tf32(v.z), f2tf32(v.w) };
            *(uint4*)&Bs[r][c4] = u;
        }
        __syncthreads();

        #pragma unroll
        for (int kk = 0; kk < 32; kk += 8) {
            unsigned a[4][4], b[4][2];
            #pragma unroll
            for (int mt = 0; mt < 4; mt++) {
                int row = wm + mt * 16 + g;
                a[mt][0] = As[row    ][kk + tg    ];
                a[mt][1] = As[row + 8][kk + tg    ];
                a[mt][2] = As[row    ][kk + tg + 4];
                a[mt][3] = As[row + 8][kk + tg + 4];
            }
            #pragma unroll
            for (int nt = 0; nt < 4; nt++) {
                int col = wn + nt * 8 + g;
                b[nt][0] = Bs[kk + tg    ][col];
                b[nt][1] = Bs[kk + tg + 4][col];
            }
            #pragma unroll
            for (int mt = 0; mt < 4; mt++)
                #pragma unroll
                for (int nt = 0; nt < 4; nt++)
                    mma_tf32(c[mt * 4 + nt],
                             a[mt][0], a[mt][1], a[mt][2], a[mt][3],
                             b[nt][0], b[nt][1]);
        }
        __syncthreads();
    }

    #pragma unroll
    for (int mt = 0; mt < 4; mt++) {
        #pragma unroll
        for (int nt = 0; nt < 4; nt++) {
            int col = bn + wn + nt * 8 + tg * 2;
            float b0 = bo[col], b1 = bo[col + 1];
            #pragma unroll
            for (int half = 0; half < 2; half++) {
                int row = bm + wm + mt * 16 + g + half * 8;
                float* p = &out[(size_t)row * DOUT + col];
                p[0] = c[mt * 4 + nt][half * 2 + 0] + b0;
                p[1] = c[mt * 4 + nt][half * 2 + 1] + b1;
            }
        }
    }
}

// ---------------------------------------------------------------------------
// Tensor-core flash attention. R12 change: Q hi/lo split DROPPED — Q stored
// pre-converted tf32 like K/V, S = single MMA per kk (halves S-GEMM work and
// removes all CVT/FSUB from the hot loop; S now carries Q+K single roundings,
// ~sqrt(2)x prior S error, budgeted). SMEM 113KB, 2 blocks/SM. Largest-first
// block order.
// NOTE: the Ks fragment read MUST stay transposed (Ks[col*68 + kk+tg]) —
// for S = Q K^T the MMA reduction dim is d, keys are the n dim.
// ---------------------------------------------------------------------------
#define QS_OFF 0
#define KS_OFF (128*68)
#define VS_OFF (KS_OFF + 64*68)
#define PS_OFF (VS_OFF + 64*68)
#define RS_OFF (PS_OFF + 128*68)
#define LS_OFF (RS_OFF + 2048)
#define ATTN_SMEM_FLOATS (LS_OFF + 128)
#define ATTN_SMEM_BYTES (ATTN_SMEM_FLOATS * 4)

__global__ __launch_bounds__(256) void attn_tc(
    const float* __restrict__ wp,
    const float* __restrict__ vp)
{
    extern __shared__ float sm[];
    unsigned* Qs = (unsigned*)sm + QS_OFF;
    unsigned* Ks = (unsigned*)sm + KS_OFF;
    unsigned* Vs = (unsigned*)sm + VS_OFF;
    unsigned* Ps = (unsigned*)sm + PS_OFF;
    float*    Rs = sm + RS_OFF;
    float*    Ls = sm + LS_OFF;

    const int qb  = (NN / 128 - 1) - blockIdx.x;   // largest-first
    const int h   = blockIdx.y;
    const int b   = blockIdx.z;
    const int tid = threadIdx.x;
    const int warp = tid >> 5;
    const int lane = tid & 31;
    const int g  = lane >> 2;
    const int tg = lane & 3;
    const int wm = (warp >> 1) * 32;
    const int wn = (warp & 1) * 32;

    const size_t head_off = (size_t)(b * HH + h) * NN * HD;
    const float* qbase = g_q + head_off;
    const float* kbase = g_k + head_off;
    const float* vbase = g_v + head_off;

    const float wh = wp[h];
    const float vh = vp[h];
    const float c1 = 1.f + __expf(vh);

    for (int i = tid; i < NN; i += 256)
        Rs[i] = c1 / (1.f + __expf(vh - wh * (float)i)) * 0.125f;
    if (tid < 128) Ls[tid] = 0.f;

    // Load Q tile pre-converted to tf32 (single rounding)
    #pragma unroll
    for (int s = 0; s < 8; s++) {
        int slot = tid + s * 256;
        int r  = slot >> 4;
        int c4 = (slot & 15) << 2;
        float4 v = *(const float4*)&qbase[(size_t)(qb * 128 + r) * HD + c4];
        uint4 u = { f2tf32(v.x), f2tf32(v.y), f2tf32(v.z), f2tf32(v.w) };
        *(uint4*)&Qs[r * 68 + c4] = u;
    }
    __syncthreads();

    float co[2][4][4];
    #pragma unroll
    for (int mt = 0; mt < 2; mt++)
        #pragma unroll
        for (int nt = 0; nt < 4; nt++)
            #pragma unroll
            for (int i = 0; i < 4; i++) co[mt][nt][i] = 0.f;

    const int ktmax = (qb + 1) * 2;
    for (int kt = 0; kt < ktmax; kt++) {
        const int k0 = kt * 64;

        #pragma unroll
        for (int s = 0; s < 4; s++) {
            int slot = tid + s * 256;
            int r  = slot >> 4;
            int c4 = (slot & 15) << 2;
            float4 kv = *(const float4*)&kbase[(size_t)(k0 + r) * HD + c4];
            float4 vv = *(const float4*)&vbase[(size_t)(k0 + r) * HD + c4];
            uint4 ku = { f2tf32(kv.x), f2tf32(kv.y), f2tf32(kv.z), f2tf32(kv.w) };
            uint4 vu = { f2tf32(vv.x), f2tf32(vv.y), f2tf32(vv.z), f2tf32(vv.w) };
            *(uint4*)&Ks[r * 68 + c4] = ku;
            *(uint4*)&Vs[r * 68 + c4] = vu;
        }
        __syncthreads();

        float cs[2][4][4];
        #pragma unroll
        for (int mt = 0; mt < 2; mt++)
            #pragma unroll
            for (int nt = 0; nt < 4; nt++)
                #pragma unroll
                for (int i = 0; i < 4; i++) cs[mt][nt][i] = 0.f;

        #pragma unroll
        for (int kk = 0; kk < 64; kk += 8) {
            unsigned a[2][4], bb[4][2];
            #pragma unroll
            for (int mt = 0; mt < 2; mt++) {
                int row = wm + mt * 16 + g;
                a[mt][0] = Qs[row * 68 + kk + tg];
                a[mt][1] = Qs[(row + 8) * 68 + kk + tg];
                a[mt][2] = Qs[row * 68 + kk + tg + 4];
                a[mt][3] = Qs[(row + 8) * 68 + kk + tg + 4];
            }
            #pragma unroll
            for (int nt = 0; nt < 4; nt++) {
                int col = wn + nt * 8 + g;   // key index within tile
                bb[nt][0] = Ks[col * 68 + kk + tg    ];
                bb[nt][1] = Ks[col * 68 + kk + tg + 4];
            }
            #pragma unroll
            for (int mt = 0; mt < 2; mt++)
                #pragma unroll
                for (int nt = 0; nt < 4; nt++)
                    mma_tf32(cs[mt][nt],
                             a[mt][0], a[mt][1], a[mt][2], a[mt][3],
                             bb[nt][0], bb[nt][1]);
        }

        float rp[2][2] = {{0.f, 0.f}, {0.f, 0.f}};
        #pragma unroll
        for (int mt = 0; mt < 2; mt++) {
            #pragma unroll
            for (int nt = 0; nt < 4; nt++) {
                #pragma unroll
                for (int i = 0; i < 4; i++) {
                    int half = i >> 1;
                    int row_l = wm + mt * 16 + g + half * 8;
                    int col = wn + nt * 8 + tg * 2 + (i & 1);
                    int R = (qb * 128 + row_l) - (k0 + col);
                    float s = fmaxf(cs[mt][nt][i], 0.f);
                    float p = (R >= 0) ? __expf(s * Rs[R]) : 0.f;
                    unsigned pt = f2tf32(p);
                    Ps[row_l * 68 + col] = pt;
                    rp[mt][half] += __uint_as_float(pt);
                }
            }
        }
        #pragma unroll
        for (int mt = 0; mt < 2; mt++)
            #pragma unroll
            for (int half = 0; half < 2; half++) {
                float v = rp[mt][half];
                v += __shfl_xor_sync(0xffffffff, v, 1);
                v += __shfl_xor_sync(0xffffffff, v, 2);
                if (tg == 0)
                    atomicAdd(&Ls[wm + mt * 16 + g + half * 8], v);
            }
        __syncthreads();

        #pragma unroll
        for (int kk = 0; kk < 64; kk += 8) {
            unsigned pa[2][4], bb[4][2];
            #pragma unroll
            for (int mt = 0; mt < 2; mt++) {
                int row = wm + mt * 16 + g;
                pa[mt][0] = Ps[row * 68 + kk + tg];
                pa[mt][1] = Ps[(row + 8) * 68 + kk + tg];
                pa[mt][2] = Ps[row * 68 + kk + tg + 4];
                pa[mt][3] = Ps[(row + 8) * 68 + kk + tg + 4];
            }
            #pragma unroll
            for (int nt = 0; nt < 4; nt++) {
                int col = wn + nt * 8 + g;   // d index
                bb[nt][0] = Vs[(kk + tg) * 68 + col];
                bb[nt][1] = Vs[(kk + tg + 4) * 68 + col];
            }
            #pragma unroll
            for (int mt = 0; mt < 2; mt++)
                #pragma unroll
                for (int nt = 0; nt < 4; nt++)
                    mma_tf32(co[mt][nt],
                             pa[mt][0], pa[mt][1], pa[mt][2], pa[mt][3],
                             bb[nt][0], bb[nt][1]);
        }
        __syncthreads();
    }

    #pragma unroll
    for (int mt = 0; mt < 2; mt++) {
        #pragma unroll
        for (int half = 0; half < 2; half++) {
            int row_l = wm + mt * 16 + g + half * 8;
            float inv = 1.f / Ls[row_l];
            int n_ = qb * 128 + row_l;
            float* op = g_ctx + ((size_t)(b * NN + n_) * DOUT) + h * HD;
            #pragma unroll
            for (int nt = 0; nt < 4; nt++) {
                int col = wn + nt * 8 + tg * 2;
                op[col]     = co[mt][nt][half * 2 + 0] * inv;
                op[col + 1] = co[mt][nt][half * 2 + 1] * inv;
            }
        }
    }
}

// ---------------------------------------------------------------------------
extern "C" void kernel_launch(void* const* d_in, const int* in_sizes, int n_in,
                              void* d_out, int out_size)
{
    const float* x  = (const float*)d_in[0];
    const float* Wq = (const float*)d_in[1];
    const float* Wk = (const float*)d_in[2];
    const float* Wv = (const float*)d_in[3];
    const float* Wo = (const float*)d_in[4];
    const float* bo = (const float*)d_in[5];
    const float* w  = (const float*)d_in[6];
    const float* v  = (const float*)d_in[7];
    float* out = (float*)d_out;

    cudaFuncSetAttribute(attn_tc,
        cudaFuncAttributeMaxDynamicSharedMemorySize, ATTN_SMEM_BYTES);

    dim3 g1(DOUT / 128, (BB * NN) / 128, 3);
    qkv_gemm_tc<<<g1, 256>>>(x, Wq, Wk, Wv);

    dim3 g2(NN / 128, HH, BB);
    attn_tc<<<g2, 256, ATTN_SMEM_BYTES>>>(w, v);

    dim3 g3(DOUT / 128, (BB * NN) / 128, 1);
    out_gemm_tc<<<g3, 256>>>(Wo, bo, out);
}

// round 14
// speedup vs baseline: 1.3574x; 1.0233x over previous
#include <cuda_runtime.h>

#define BB 2
#define NN 2048
#define DIN 1024
#define DOUT 1024
#define HH 16
#define HD 64

// Scratch (static device allocations — allowed)
__device__ float g_q[BB*HH*NN*HD];
__device__ float g_k[BB*HH*NN*HD];
__device__ float g_v[BB*HH*NN*HD];
__device__ float g_ctx[BB*NN*DOUT];

__device__ __forceinline__ unsigned f2tf32(float f) {
    unsigned r;
    asm("cvt.rna.tf32.f32 %0, %1;" : "=r"(r) : "f"(f));
    return r;
}

__device__ __forceinline__ void mma_tf32(float c[4],
    unsigned a0, unsigned a1, unsigned a2, unsigned a3,
    unsigned b0, unsigned b1)
{
    asm volatile(
        "mma.sync.aligned.m16n8k8.row.col.f32.tf32.tf32.f32 "
        "{%0,%1,%2,%3}, {%4,%5,%6,%7}, {%8,%9}, {%0,%1,%2,%3};"
        : "+f"(c[0]), "+f"(c[1]), "+f"(c[2]), "+f"(c[3])
        : "r"(a0), "r"(a1), "r"(a2), "r"(a3), "r"(b0), "r"(b1));
}

__device__ __forceinline__ void cp16(void* dst, const void* src) {
    unsigned d = (unsigned)__cvta_generic_to_shared(dst);
    asm volatile("cp.async.cg.shared.global [%0], [%1], 16;" :: "r"(d), "l"(src));
}
#define CP_COMMIT() asm volatile("cp.async.commit_group;")
#define CP_WAIT0()  asm volatile("cp.async.wait_group 0;")

// ---------------------------------------------------------------------------
// Fused QKV GEMM, tf32 MMA, cp.async DOUBLE-BUFFERED tiles (raw fp32 in SMEM,
// tf32 conversion at fragment read — numerically identical to pre-convert).
// 72KB SMEM; __launch_bounds__(256,2) pins 128 regs -> 2 blocks/SM.
// One __syncthreads per K-tile.
// ---------------------------------------------------------------------------
__global__ __launch_bounds__(256, 2) void qkv_gemm_tc(
    const float* __restrict__ x,
    const float* __restrict__ Wq,
    const float* __restrict__ Wk,
    const float* __restrict__ Wv)
{
    const float* W = (blockIdx.z == 0) ? Wq : (blockIdx.z == 1 ? Wk : Wv);
    float* out = (blockIdx.z == 0) ? g_q : (blockIdx.z == 1 ? g_k : g_v);

    __shared__ float As[2][128][36];
    __shared__ float Bs[2][32][136];

    const int tid  = threadIdx.x;
    const int warp = tid >> 5;
    const int lane = tid & 31;
    const int g    = lane >> 2;
    const int tg   = lane & 3;
    const int wm   = (warp >> 2) * 64;
    const int wn   = (warp & 3) * 32;
    const int bm   = blockIdx.y * 128;
    const int bn   = blockIdx.x * 128;

    // load-slot geometry (4 x 16B per thread per tile for each of A, B)
    int a_r[4], a_c[4], b_r[4], b_c[4];
    #pragma unroll
    for (int s = 0; s < 4; s++) {
        int slot = tid + s * 256;
        a_r[s] = slot >> 3;              // 0..127
        a_c[s] = (slot & 7) << 2;        // 0..28
        b_r[s] = slot >> 5;              // 0..31
        b_c[s] = (slot & 31) << 2;       // 0..124
    }

    float c[16][4];
    #pragma unroll
    for (int t = 0; t < 16; t++)
        #pragma unroll
        for (int i = 0; i < 4; i++) c[t][i] = 0.f;

    // prologue: tile 0 -> buffer 0
    #pragma unroll
    for (int s = 0; s < 4; s++) {
        cp16(&As[0][a_r[s]][a_c[s]], &x[(size_t)(bm + a_r[s]) * DIN + a_c[s]]);
        cp16(&Bs[0][b_r[s]][b_c[s]], &W[(size_t)b_r[s] * DOUT + bn + b_c[s]]);
    }
    CP_COMMIT();
    CP_WAIT0();
    __syncthreads();

    const int NKT = DIN / 32;
    for (int kt = 0; kt < NKT; kt++) {
        const int buf = kt & 1;
        if (kt + 1 < NKT) {
            const int k0n = (kt + 1) * 32;
            #pragma unroll
            for (int s = 0; s < 4; s++) {
                cp16(&As[buf ^ 1][a_r[s]][a_c[s]],
                     &x[(size_t)(bm + a_r[s]) * DIN + k0n + a_c[s]]);
                cp16(&Bs[buf ^ 1][b_r[s]][b_c[s]],
                     &W[(size_t)(k0n + b_r[s]) * DOUT + bn + b_c[s]]);
            }
            CP_COMMIT();
        }

        #pragma unroll
        for (int kk = 0; kk < 32; kk += 8) {
            unsigned a[4][4], b[4][2];
            #pragma unroll
            for (int mt = 0; mt < 4; mt++) {
                int row = wm + mt * 16 + g;
                a[mt][0] = f2tf32(As[buf][row    ][kk + tg    ]);
                a[mt][1] = f2tf32(As[buf][row + 8][kk + tg    ]);
                a[mt][2] = f2tf32(As[buf][row    ][kk + tg + 4]);
                a[mt][3] = f2tf32(As[buf][row + 8][kk + tg + 4]);
            }
            #pragma unroll
            for (int nt = 0; nt < 4; nt++) {
                int col = wn + nt * 8 + g;
                b[nt][0] = f2tf32(Bs[buf][kk + tg    ][col]);
                b[nt][1] = f2tf32(Bs[buf][kk + tg + 4][col]);
            }
            #pragma unroll
            for (int mt = 0; mt < 4; mt++)
                #pragma unroll
                for (int nt = 0; nt < 4; nt++)
                    mma_tf32(c[mt * 4 + nt],
                             a[mt][0], a[mt][1], a[mt][2], a[mt][3],
                             b[nt][0], b[nt][1]);
        }

        if (kt + 1 < NKT) CP_WAIT0();
        __syncthreads();
    }

    #pragma unroll
    for (int mt = 0; mt < 4; mt++) {
        #pragma unroll
        for (int nt = 0; nt < 4; nt++) {
            int col = bn + wn + nt * 8 + tg * 2;
            int h_ = col >> 6;
            int d_ = col & 63;
            #pragma unroll
            for (int half = 0; half < 2; half++) {
                int row = bm + wm + mt * 16 + g + half * 8;
                int b_ = row >> 11;
                int n_ = row & 2047;
                float* p = &out[(((size_t)(b_ * HH + h_) * NN) + n_) * HD + d_];
                p[0] = c[mt * 4 + nt][half * 2 + 0];
                p[1] = c[mt * 4 + nt][half * 2 + 1];
            }
        }
    }
}

// ---------------------------------------------------------------------------
// Output GEMM: same cp.async double-buffered structure.
// ---------------------------------------------------------------------------
__global__ __launch_bounds__(256, 2) void out_gemm_tc(
    const float* __restrict__ Wo,
    const float* __restrict__ bo,
    float* __restrict__ out)
{
    __shared__ float As[2][128][36];
    __shared__ float Bs[2][32][136];

    const int tid  = threadIdx.x;
    const int warp = tid >> 5;
    const int lane = tid & 31;
    const int g    = lane >> 2;
    const int tg   = lane & 3;
    const int wm   = (warp >> 2) * 64;
    const int wn   = (warp & 3) * 32;
    const int bm   = blockIdx.y * 128;
    const int bn   = blockIdx.x * 128;

    int a_r[4], a_c[4], b_r[4], b_c[4];
    #pragma unroll
    for (int s = 0; s < 4; s++) {
        int slot = tid + s * 256;
        a_r[s] = slot >> 3;
        a_c[s] = (slot & 7) << 2;
        b_r[s] = slot >> 5;
        b_c[s] = (slot & 31) << 2;
    }

    float c[16][4];
    #pragma unroll
    for (int t = 0; t < 16; t++)
        #pragma unroll
        for (int i = 0; i < 4; i++) c[t][i] = 0.f;

    #pragma unroll
    for (int s = 0; s < 4; s++) {
        cp16(&As[0][a_r[s]][a_c[s]], &g_ctx[(size_t)(bm + a_r[s]) * DOUT + a_c[s]]);
        cp16(&Bs[0][b_r[s]][b_c[s]], &Wo[(size_t)b_r[s] * DOUT + bn + b_c[s]]);
    }
    CP_COMMIT();
    CP_WAIT0();
    __syncthreads();

    const int NKT = DOUT / 32;
    for (int kt = 0; kt < NKT; kt++) {
        const int buf = kt & 1;
        if (kt + 1 < NKT) {
            const int k0n = (kt + 1) * 32;
            #pragma unroll
            for (int s = 0; s < 4; s++) {
                cp16(&As[buf ^ 1][a_r[s]][a_c[s]],
                     &g_ctx[(size_t)(bm + a_r[s]) * DOUT + k0n + a_c[s]]);
                cp16(&Bs[buf ^ 1][b_r[s]][b_c[s]],
                     &Wo[(size_t)(k0n + b_r[s]) * DOUT + bn + b_c[s]]);
            }
            CP_COMMIT();
        }

        #pragma unroll
        for (int kk = 0; kk < 32; kk += 8) {
            unsigned a[4][4], b[4][2];
            #pragma unroll
            for (int mt = 0; mt < 4; mt++) {
                int row = wm + mt * 16 + g;
                a[mt][0] = f2tf32(As[buf][row    ][kk + tg    ]);
                a[mt][1] = f2tf32(As[buf][row + 8][kk + tg    ]);
                a[mt][2] = f2tf32(As[buf][row    ][kk + tg + 4]);
                a[mt][3] = f2tf32(As[buf][row + 8][kk + tg + 4]);
            }
            #pragma unroll
            for (int nt = 0; nt < 4; nt++) {
                int col = wn + nt * 8 + g;
                b[nt][0] = f2tf32(Bs[buf][kk + tg    ][col]);
                b[nt][1] = f2tf32(Bs[buf][kk + tg + 4][col]);
            }
            #pragma unroll
            for (int mt = 0; mt < 4; mt++)
                #pragma unroll
                for (int nt = 0; nt < 4; nt++)
                    mma_tf32(c[mt * 4 + nt],
                             a[mt][0], a[mt][1], a[mt][2], a[mt][3],
                             b[nt][0], b[nt][1]);
        }

        if (kt + 1 < NKT) CP_WAIT0();
        __syncthreads();
    }

    #pragma unroll
    for (int mt = 0; mt < 4; mt++) {
        #pragma unroll
        for (int nt = 0; nt < 4; nt++) {
            int col = bn + wn + nt * 8 + tg * 2;
            float b0 = bo[col], b1 = bo[col + 1];
            #pragma unroll
            for (int half = 0; half < 2; half++) {
                int row = bm + wm + mt * 16 + g + half * 8;
                float* p = &out[(size_t)row * DOUT + col];
                p[0] = c[mt * 4 + nt][half * 2 + 0] + b0;
                p[1] = c[mt * 4 + nt][half * 2 + 1] + b1;
            }
        }
    }
}

// ---------------------------------------------------------------------------
// Tensor-core flash attention. Unchanged from R12 (passing at 578us total):
// Q/K/V/P all single-rounded tf32 in SMEM, 113KB, 2 blocks/SM, largest-first.
// NOTE: the Ks fragment read MUST stay transposed (Ks[col*68 + kk+tg]) —
// for S = Q K^T the MMA reduction dim is d, keys are the n dim.
// ---------------------------------------------------------------------------
#define QS_OFF 0
#define KS_OFF (128*68)
#define VS_OFF (KS_OFF + 64*68)
#define PS_OFF (VS_OFF + 64*68)
#define RS_OFF (PS_OFF + 128*68)
#define LS_OFF (RS_OFF + 2048)
#define ATTN_SMEM_FLOATS (LS_OFF + 128)
#define ATTN_SMEM_BYTES (ATTN_SMEM_FLOATS * 4)

__global__ __launch_bounds__(256) void attn_tc(
    const float* __restrict__ wp,
    const float* __restrict__ vp)
{
    extern __shared__ float sm[];
    unsigned* Qs = (unsigned*)sm + QS_OFF;
    unsigned* Ks = (unsigned*)sm + KS_OFF;
    unsigned* Vs = (unsigned*)sm + VS_OFF;
    unsigned* Ps = (unsigned*)sm + PS_OFF;
    float*    Rs = sm + RS_OFF;
    float*    Ls = sm + LS_OFF;

    const int qb  = (NN / 128 - 1) - blockIdx.x;   // largest-first
    const int h   = blockIdx.y;
    const int b   = blockIdx.z;
    const int tid = threadIdx.x;
    const int warp = tid >> 5;
    const int lane = tid & 31;
    const int g  = lane >> 2;
    const int tg = lane & 3;
    const int wm = (warp >> 1) * 32;
    const int wn = (warp & 1) * 32;

    const size_t head_off = (size_t)(b * HH + h) * NN * HD;
    const float* qbase = g_q + head_off;
    const float* kbase = g_k + head_off;
    const float* vbase = g_v + head_off;

    const float wh = wp[h];
    const float vh = vp[h];
    const float c1 = 1.f + __expf(vh);

    for (int i = tid; i < NN; i += 256)
        Rs[i] = c1 / (1.f + __expf(vh - wh * (float)i)) * 0.125f;
    if (tid < 128) Ls[tid] = 0.f;

    #pragma unroll
    for (int s = 0; s < 8; s++) {
        int slot = tid + s * 256;
        int r  = slot >> 4;
        int c4 = (slot & 15) << 2;
        float4 v = *(const float4*)&qbase[(size_t)(qb * 128 + r) * HD + c4];
        uint4 u = { f2tf32(v.x), f2tf32(v.y), f2tf32(v.z), f2tf32(v.w) };
        *(uint4*)&Qs[r * 68 + c4] = u;
    }
    __syncthreads();

    float co[2][4][4];
    #pragma unroll
    for (int mt = 0; mt < 2; mt++)
        #pragma unroll
        for (int nt = 0; nt < 4; nt++)
            #pragma unroll
            for (int i = 0; i < 4; i++) co[mt][nt][i] = 0.f;

    const int ktmax = (qb + 1) * 2;
    for (int kt = 0; kt < ktmax; kt++) {
        const int k0 = kt * 64;

        #pragma unroll
        for (int s = 0; s < 4; s++) {
            int slot = tid + s * 256;
            int r  = slot >> 4;
            int c4 = (slot & 15) << 2;
            float4 kv = *(const float4*)&kbase[(size_t)(k0 + r) * HD + c4];
            float4 vv = *(const float4*)&vbase[(size_t)(k0 + r) * HD + c4];
            uint4 ku = { f2tf32(kv.x), f2tf32(kv.y), f2tf32(kv.z), f2tf32(kv.w) };
            uint4 vu = { f2tf32(vv.x), f2tf32(vv.y), f2tf32(vv.z), f2tf32(vv.w) };
            *(uint4*)&Ks[r * 68 + c4] = ku;
            *(uint4*)&Vs[r * 68 + c4] = vu;
        }
        __syncthreads();

        float cs[2][4][4];
        #pragma unroll
        for (int mt = 0; mt < 2; mt++)
            #pragma unroll
            for (int nt = 0; nt < 4; nt++)
                #pragma unroll
                for (int i = 0; i < 4; i++) cs[mt][nt][i] = 0.f;

        #pragma unroll
        for (int kk = 0; kk < 64; kk += 8) {
            unsigned a[2][4], bb[4][2];
            #pragma unroll
            for (int mt = 0; mt < 2; mt++) {
                int row = wm + mt * 16 + g;
                a[mt][0] = Qs[row * 68 + kk + tg];
                a[mt][1] = Qs[(row + 8) * 68 + kk + tg];
                a[mt][2] = Qs[row * 68 + kk + tg + 4];
                a[mt][3] = Qs[(row + 8) * 68 + kk + tg + 4];
            }
            #pragma unroll
            for (int nt = 0; nt < 4; nt++) {
                int col = wn + nt * 8 + g;   // key index within tile
                bb[nt][0] = Ks[col * 68 + kk + tg    ];
                bb[nt][1] = Ks[col * 68 + kk + tg + 4];
            }
            #pragma unroll
            for (int mt = 0; mt < 2; mt++)
                #pragma unroll
                for (int nt = 0; nt < 4; nt++)
                    mma_tf32(cs[mt][nt],
                             a[mt][0], a[mt][1], a[mt][2], a[mt][3],
                             bb[nt][0], bb[nt][1]);
        }

        float rp[2][2] = {{0.f, 0.f}, {0.f, 0.f}};
        #pragma unroll
        for (int mt = 0; mt < 2; mt++) {
            #pragma unroll
            for (int nt = 0; nt < 4; nt++) {
                #pragma unroll
                for (int i = 0; i < 4; i++) {
                    int half = i >> 1;
                    int row_l = wm + mt * 16 + g + half * 8;
                    int col = wn + nt * 8 + tg * 2 + (i & 1);
                    int R = (qb * 128 + row_l) - (k0 + col);
                    float s = fmaxf(cs[mt][nt][i], 0.f);
                    float p = (R >= 0) ? __expf(s * Rs[R]) : 0.f;
                    unsigned pt = f2tf32(p);
                    Ps[row_l * 68 + col] = pt;
                    rp[mt][half] += __uint_as_float(pt);
                }
            }
        }
        #pragma unroll
        for (int mt = 0; mt < 2; mt++)
            #pragma unroll
            for (int half = 0; half < 2; half++) {
                float v = rp[mt][half];
                v += __shfl_xor_sync(0xffffffff, v, 1);
                v += __shfl_xor_sync(0xffffffff, v, 2);
                if (tg == 0)
                    atomicAdd(&Ls[wm + mt * 16 + g + half * 8], v);
            }
        __syncthreads();

        #pragma unroll
        for (int kk = 0; kk < 64; kk += 8) {
            unsigned pa[2][4], bb[4][2];
            #pragma unroll
            for (int mt = 0; mt < 2; mt++) {
                int row = wm + mt * 16 + g;
                pa[mt][0] = Ps[row * 68 + kk + tg];
                pa[mt][1] = Ps[(row + 8) * 68 + kk + tg];
                pa[mt][2] = Ps[row * 68 + kk + tg + 4];
                pa[mt][3] = Ps[(row + 8) * 68 + kk + tg + 4];
            }
            #pragma unroll
            for (int nt = 0; nt < 4; nt++) {
                int col = wn + nt * 8 + g;   // d index
                bb[nt][0] = Vs[(kk + tg) * 68 + col];
                bb[nt][1] = Vs[(kk + tg + 4) * 68 + col];
            }
            #pragma unroll
            for (int mt = 0; mt < 2; mt++)
                #pragma unroll
                for (int nt = 0; nt < 4; nt++)
                    mma_tf32(co[mt][nt],
                             pa[mt][0], pa[mt][1], pa[mt][2], pa[mt][3],
                             bb[nt][0], bb[nt][1]);
        }
        __syncthreads();
    }

    #pragma unroll
    for (int mt = 0; mt < 2; mt++) {
        #pragma unroll
        for (int half = 0; half < 2; half++) {
            int row_l = wm + mt * 16 + g + half * 8;
            float inv = 1.f / Ls[row_l];
            int n_ = qb * 128 + row_l;
            float* op = g_ctx + ((size_t)(b * NN + n_) * DOUT) + h * HD;
            #pragma unroll
            for (int nt = 0; nt < 4; nt++) {
                int col = wn + nt * 8 + tg * 2;
                op[col]     = co[mt][nt][half * 2 + 0] * inv;
                op[col + 1] = co[mt][nt][half * 2 + 1] * inv;
            }
        }
    }
}

// ---------------------------------------------------------------------------
extern "C" void kernel_launch(void* const* d_in, const int* in_sizes, int n_in,
                              void* d_out, int out_size)
{
    const float* x  = (const float*)d_in[0];
    const float* Wq = (const float*)d_in[1];
    const float* Wk = (const float*)d_in[2];
    const float* Wv = (const float*)d_in[3];
    const float* Wo = (const float*)d_in[4];
    const float* bo = (const float*)d_in[5];
    const float* w  = (const float*)d_in[6];
    const float* v  = (const float*)d_in[7];
    float* out = (float*)d_out;

    cudaFuncSetAttribute(attn_tc,
        cudaFuncAttributeMaxDynamicSharedMemorySize, ATTN_SMEM_BYTES);

    dim3 g1(DOUT / 128, (BB * NN) / 128, 3);
    qkv_gemm_tc<<<g1, 256>>>(x, Wq, Wk, Wv);

    dim3 g2(NN / 128, HH, BB);
    attn_tc<<<g2, 256, ATTN_SMEM_BYTES>>>(w, v);

    dim3 g3(DOUT / 128, (BB * NN) / 128, 1);
    out_gemm_tc<<<g3, 256>>>(Wo, bo, out);
}